// round 14
// baseline (speedup 1.0000x reference)
#include <cuda_runtime.h>
#include <math.h>

// ---------------------------------------------------------------------------
// Problem constants
// ---------------------------------------------------------------------------
#define B_ 4
#define V_ 8
#define D_ 64
#define N_ 16
#define H_ 32
#define W_ 32
#define HW 1024
#define EPS 1e-5f

// smem plane geometry for the gather: row stride 34 -> bank = (2y+x) % 32,
// conflict-free along the +-45 deg tap diagonals.
#define RSTRIDE 34
#define PLANE   (32 * RSTRIDE)   // 1088 floats

// ---------------------------------------------------------------------------
// Scratch (device globals; no dynamic allocation allowed)
// ---------------------------------------------------------------------------
__device__ float  g_delta[B_ * D_ * HW];   // clipped softplus delta
__device__ float  g_du   [B_ * D_ * HW];   // delta * u_t
__device__ float  g_Bv   [B_ * N_ * HW];   // conv_B(u_norm)
__device__ float  g_Cv   [B_ * N_ * HW];   // conv_C(u_norm)
__device__ float  g_A    [D_ * N_];        // -exp(log_A_real)
__device__ float2 g_stat [B_ * 4];         // per (b, group): (mu, rsqrt)
__device__ float4 g_wtab [V_ * HW];        // bilinear weights (masked)
__device__ short4 g_itab [V_ * HW];        // padded-smem tap offsets (stride 34)

// ---------------------------------------------------------------------------
// Kernel 0: fused GN-stats (blocks 0..15) + init tables (blocks 16..23)
// 1024 threads/block for memory-level parallelism.
// ---------------------------------------------------------------------------
__global__ __launch_bounds__(1024)
void k_stats_init(const float* __restrict__ u, const float* __restrict__ log_A_real) {
    int blk = blockIdx.x;
    int tid = threadIdx.x;

    if (blk < 16) {
        const float4* base = (const float4*)(u + ((size_t)blk << 14));
        float s = 0.f, ss = 0.f;
#pragma unroll
        for (int it = 0; it < 4; it++) {
            float4 v = base[tid + it * 1024];
            s += v.x + v.y + v.z + v.w;
            ss = fmaf(v.x, v.x, ss);
            ss = fmaf(v.y, v.y, ss);
            ss = fmaf(v.z, v.z, ss);
            ss = fmaf(v.w, v.w, ss);
        }
        for (int o = 16; o; o >>= 1) {
            s  += __shfl_down_sync(0xffffffffu, s, o);
            ss += __shfl_down_sync(0xffffffffu, ss, o);
        }
        __shared__ float shs[32], shss[32];
        int wid = tid >> 5, lid = tid & 31;
        if (lid == 0) { shs[wid] = s; shss[wid] = ss; }
        __syncthreads();
        if (tid == 0) {
            float S = 0.f, SS = 0.f;
#pragma unroll
            for (int i = 0; i < 32; i++) { S += shs[i]; SS += shss[i]; }
            float mu  = S / 16384.0f;
            float var = SS / 16384.0f - mu * mu;
            g_stat[blk] = make_float2(mu, rsqrtf(var + EPS));
        }
        return;
    }

    int gid = (blk - 16) * 1024 + tid;      // 0..8191 ; one v per block
    if (gid < D_ * N_) {
        g_A[gid] = -expf(log_A_real[gid]);
    }

    {
        int v = gid >> 10;
        int p = gid & 1023;
        int h = p >> 5, w = p & 31;

        float c, sn;
        if ((v & 1) == 0) {
            // exact axis rotations: 0, -90, -180, -270 deg
            int q = v >> 1;
            c  = (q == 0) ? 1.f : (q == 2) ? -1.f : 0.f;
            sn = (q == 1) ? -1.f : (q == 3) ? 1.f : 0.f;
        } else {
            float ang = (float)v * -0.78539816339744830961f;
            c  = cosf(ang);
            sn = sinf(ang);
        }

        float X = ((w + 0.5f) * 2.0f) / 32.0f - 1.0f;   // exact in fp32
        float Y = ((h + 0.5f) * 2.0f) / 32.0f - 1.0f;
        float gx = c * X - sn * Y;
        float gy = sn * X + c * Y;
        float ix = (gx + 1.0f) * 16.0f - 0.5f;
        float iy = (gy + 1.0f) * 16.0f - 0.5f;

        float x0f = floorf(ix), y0f = floorf(iy);
        float wx1 = ix - x0f, wy1 = iy - y0f;
        float wx0 = 1.0f - wx1, wy0 = 1.0f - wy1;
        int x0 = (int)x0f, y0 = (int)y0f;
        int x1 = x0 + 1, y1 = y0 + 1;

        auto ok = [](int yy, int xx) { return yy >= 0 && yy < H_ && xx >= 0 && xx < W_; };
        float w00 = ok(y0, x0) ? wy0 * wx0 : 0.0f;
        float w01 = ok(y0, x1) ? wy0 * wx1 : 0.0f;
        float w10 = ok(y1, x0) ? wy1 * wx0 : 0.0f;
        float w11 = ok(y1, x1) ? wy1 * wx1 : 0.0f;

        auto cl = [](int v_, int hi) { return v_ < 0 ? 0 : (v_ > hi ? hi : v_); };
        int y0c = cl(y0, H_ - 1), y1c = cl(y1, H_ - 1);
        int x0c = cl(x0, W_ - 1), x1c = cl(x1, W_ - 1);
        short i00 = (short)(y0c * RSTRIDE + x0c);
        short i01 = (short)(y0c * RSTRIDE + x1c);
        short i10 = (short)(y1c * RSTRIDE + x0c);
        short i11 = (short)(y1c * RSTRIDE + x1c);

        g_wtab[gid] = make_float4(w00, w01, w10, w11);
        g_itab[gid] = make_short4(i00, i01, i10, i11);
    }
}

// ---------------------------------------------------------------------------
// Kernel 1: fused 3x3 convs + inline group-norm, software-pipelined staging.
// Weight smem layout [ic][tap][j]: one LDS.128 per tap serves all 4 ocs,
// scalar FFMA accumulation (4 independent chains).
// ---------------------------------------------------------------------------
__global__ __launch_bounds__(256)
void k_conv(const float* __restrict__ wD, const float* __restrict__ bD,
            const float* __restrict__ wB, const float* __restrict__ wC,
            const float* __restrict__ u_t,
            const float* __restrict__ gw, const float* __restrict__ gb,
            const float* __restrict__ dt_bias_p) {
    int strip = blockIdx.x & 3;
    int rest  = blockIdx.x >> 2;
    int ocq   = rest % 24;
    int b     = rest / 24;
    int tid   = threadIdx.x;

    __shared__ __align__(16) float wsh[D_ * 9 * 4];  // [ic][tap][j]  9216 B
    __shared__ float buf[2][2][340];                 // 5440 B
    __shared__ float ssc[64], ssh[64];               // per-ic normalize

    // load weights: wsh[ic*36 + tap*4 + j] = W_oc(j)[ic][tap]
    for (int k = tid; k < D_ * 9 * 4; k += 256) {
        int j   = k & 3;
        int tap = (k >> 2) % 9;
        int ic  = k / 36;
        int oc  = ocq * 4 + j;
        const float* src;
        if (oc < 64)      src = wD + (size_t)oc * 576;
        else if (oc < 80) src = wB + (size_t)(oc - 64) * 576;
        else              src = wC + (size_t)(oc - 80) * 576;
        wsh[k] = src[ic * 9 + tap];
    }
    if (tid < 64) {
        float2 st = g_stat[b * 4 + (tid >> 4)];
        float sc = st.y * gw[tid];
        ssc[tid] = sc;
        ssh[tid] = gb[tid] - st.x * sc;
    }

    int h0    = strip * 8;
    int local = tid >> 5;    // 0..7
    int col   = tid & 31;

    // hoisted staging index math
    int r1 = tid / 34, c1 = tid - r1 * 34;
    int gr1 = h0 - 1 + r1, gc1 = c1 - 1;
    bool ok1 = (gr1 >= 0) && (gr1 < 32) && (gc1 >= 0) && (gc1 < 32);
    int go1 = ok1 ? gr1 * 32 + gc1 : 0;
    int k2 = tid + 256;
    bool has2 = (k2 < 340);
    int r2 = k2 / 34, c2 = k2 - r2 * 34;
    int gr2 = h0 - 1 + r2, gc2 = c2 - 1;
    bool ok2 = has2 && (gr2 >= 0) && (gr2 < 32) && (gc2 >= 0) && (gc2 < 32);
    int go2 = ok2 ? gr2 * 32 + gc2 : 0;

    const float* ubase = u_t + ((size_t)b << 16);

    float acc[4] = {0.f, 0.f, 0.f, 0.f};

    float ra0 = ok1 ? __ldg(ubase + go1)        : 0.f;
    float ra1 = ok1 ? __ldg(ubase + 1024 + go1) : 0.f;
    float rb0 = ok2 ? __ldg(ubase + go2)        : 0.f;
    float rb1 = ok2 ? __ldg(ubase + 1024 + go2) : 0.f;
    __syncthreads();

    buf[0][0][tid] = ok1 ? fmaf(ra0, ssc[0], ssh[0]) : 0.f;
    buf[0][1][tid] = ok1 ? fmaf(ra1, ssc[1], ssh[1]) : 0.f;
    if (has2) {
        buf[0][0][k2] = ok2 ? fmaf(rb0, ssc[0], ssh[0]) : 0.f;
        buf[0][1][k2] = ok2 ? fmaf(rb1, ssc[1], ssh[1]) : 0.f;
    }
    __syncthreads();

    for (int pair = 0; pair < 32; pair++) {
        int cur = pair & 1;
        int nxt = cur ^ 1;
        int icn0 = pair * 2 + 2;

        if (pair < 31) {
            const float* u0 = ubase + ((size_t)icn0 << 10);
            ra0 = ok1 ? __ldg(u0 + go1)        : 0.f;
            ra1 = ok1 ? __ldg(u0 + 1024 + go1) : 0.f;
            rb0 = ok2 ? __ldg(u0 + go2)        : 0.f;
            rb1 = ok2 ? __ldg(u0 + 1024 + go2) : 0.f;
        }

#pragma unroll
        for (int ii = 0; ii < 2; ii++) {
            int ic = pair * 2 + ii;
            const float* pb = buf[cur][ii];
            const float* wp = &wsh[ic * 36];
#pragma unroll
            for (int r = 0; r < 3; r++) {
#pragma unroll
                for (int c = 0; c < 3; c++) {
                    float t = pb[(local + r) * 34 + col + c];
                    float4 wv = *(const float4*)&wp[(r * 3 + c) * 4];
                    acc[0] = fmaf(t, wv.x, acc[0]);
                    acc[1] = fmaf(t, wv.y, acc[1]);
                    acc[2] = fmaf(t, wv.z, acc[2]);
                    acc[3] = fmaf(t, wv.w, acc[3]);
                }
            }
        }

        if (pair < 31) {
            buf[nxt][0][tid] = ok1 ? fmaf(ra0, ssc[icn0],     ssh[icn0])     : 0.f;
            buf[nxt][1][tid] = ok1 ? fmaf(ra1, ssc[icn0 + 1], ssh[icn0 + 1]) : 0.f;
            if (has2) {
                buf[nxt][0][k2] = ok2 ? fmaf(rb0, ssc[icn0],     ssh[icn0])     : 0.f;
                buf[nxt][1][k2] = ok2 ? fmaf(rb1, ssc[icn0 + 1], ssh[icn0 + 1]) : 0.f;
            }
        }
        __syncthreads();
    }

    int p = (h0 + local) * 32 + col;
    if (ocq < 16) {
        float dtb = dt_bias_p[0];
#pragma unroll
        for (int j = 0; j < 4; j++) {
            int oc = ocq * 4 + j;
            float x  = acc[j] + bD[oc] + dtb;
            float sp = fmaxf(x, 0.0f) + log1pf(expf(-fabsf(x)));
            float d  = fminf(fmaxf(sp, 1e-4f), 5.0f);
            size_t idx = ((size_t)(b * D_ + oc) << 10) + p;
            g_delta[idx] = d;
            g_du[idx]    = d * u_t[idx];
        }
    } else if (ocq < 20) {
#pragma unroll
        for (int j = 0; j < 4; j++) {
            int n = (ocq - 16) * 4 + j;
            g_Bv[((size_t)(b * N_ + n) << 10) + p] = acc[j];
        }
    } else {
#pragma unroll
        for (int j = 0; j < 4; j++) {
            int n = (ocq - 20) * 4 + j;
            g_Cv[((size_t)(b * N_ + n) << 10) + p] = acc[j];
        }
    }
}

// ---------------------------------------------------------------------------
// Kernel 2: main transport + SSM update + einsum
// grid = B*V*D = 2048 blocks, 256 threads (4 consecutive pixels/thread)
//   v=0 : identity -> pure streaming, no smem/barriers
//   v=4 : 180 deg -> reversed float4 read, no smem/barriers
//   else: DOUBLE-BUFFERED stride-34 padded-smem gather (1 barrier/phase)
// Bv/Cv loads software-pipelined one n-iteration ahead (hides L1/L2 latency).
// ---------------------------------------------------------------------------
__global__ __launch_bounds__(256)
void k_main(const float* __restrict__ s_prev,
            const float* __restrict__ u_t,
            const float* __restrict__ Dp,
            float* __restrict__ y_out,
            float* __restrict__ s_out) {
    int blk = blockIdx.x;                 // = ((b*V + v)*D + d)
    int d = blk & 63;
    int v = (blk >> 6) & 7;
    int b = blk >> 9;

    __shared__ float sp[2][4 * PLANE];    // 34816 B (double-buffered)
    __shared__ float Ash[N_];

    int tid = threadIdx.x;
    int p0  = tid * 4;

    size_t bdp = ((size_t)(b * D_ + d) << 10) + p0;
    float4 dl4 = *(const float4*)&g_delta[bdp];
    float4 du4 = *(const float4*)&g_du[bdp];
    float4 u4  = *(const float4*)&u_t[bdp];
    float dl[4] = {dl4.x, dl4.y, dl4.z, dl4.w};
    float du[4] = {du4.x, du4.y, du4.z, du4.w};

    const float* sbase = s_prev + ((size_t)blk << 14);
    float*       snb   = s_out  + ((size_t)blk << 14);
    const float* Bvb   = g_Bv + ((size_t)b << 14) + p0;
    const float* Cvb   = g_Cv + ((size_t)b << 14) + p0;

    float yacc[4] = {0.f, 0.f, 0.f, 0.f};

    // n-pipelined Bv/Cv: load n=0 now, then prefetch n+1 inside the loop
    float4 bvc = *(const float4*)&Bvb[0];
    float4 cvc = *(const float4*)&Cvb[0];

    if (v == 0 || v == 4) {
        // exact permutations: identity (v=0) or point reflection (v=4)
        bool mir = (v == 4);
        int fidx = mir ? (255 - tid) : tid;
#pragma unroll
        for (int g = 0; g < 4; g++) {
            float4 sv[4];
#pragma unroll
            for (int j = 0; j < 4; j++)
                sv[j] = __ldcs((const float4*)(sbase + ((size_t)(g * 4 + j) << 10)) + fidx);
#pragma unroll
            for (int j = 0; j < 4; j++) {
                int n = g * 4 + j;
                float4 bvn, cvn;
                if (n < 15) {
                    bvn = *(const float4*)&Bvb[(size_t)(n + 1) << 10];
                    cvn = *(const float4*)&Cvb[(size_t)(n + 1) << 10];
                }
                float A_n = __ldg(&g_A[d * N_ + n]);
                float stv[4];
                if (mir) {
                    stv[0] = sv[j].w; stv[1] = sv[j].z; stv[2] = sv[j].y; stv[3] = sv[j].x;
                } else {
                    stv[0] = sv[j].x; stv[1] = sv[j].y; stv[2] = sv[j].z; stv[3] = sv[j].w;
                }
                float bva[4] = {bvc.x, bvc.y, bvc.z, bvc.w};
                float cva[4] = {cvc.x, cvc.y, cvc.z, cvc.w};
                float sn[4];
#pragma unroll
                for (int i = 0; i < 4; i++) {
                    float ab = __expf(dl[i] * A_n);
                    sn[i] = fmaf(ab, stv[i], du[i] * bva[i]);
                    yacc[i] = fmaf(sn[i], cva[i], yacc[i]);
                }
                float4 so = make_float4(sn[0], sn[1], sn[2], sn[3]);
                __stcs((float4*)&snb[((size_t)n << 10) + p0], so);
                if (n < 15) { bvc = bvn; cvc = cvn; }
            }
        }
    } else {
        if (tid < N_) Ash[tid] = g_A[d * N_ + tid];

        float4 wt[4];
        short4 it[4];
        bool   single[4];
#pragma unroll
        for (int i = 0; i < 4; i++) {
            int tabi = (v << 10) + p0 + i;
            wt[i] = g_wtab[tabi];
            it[i] = g_itab[tabi];
            single[i] = (wt[i].y == 0.0f) && (wt[i].z == 0.0f) && (wt[i].w == 0.0f);
        }

        int soff = (p0 >> 5) * RSTRIDE + (p0 & 31);

        // prologue: load + stage phase 0 into buffer 0
        float4 pre[4];
#pragma unroll
        for (int j = 0; j < 4; j++)
            pre[j] = __ldcs((const float4*)sbase + tid + j * 256);
#pragma unroll
        for (int j = 0; j < 4; j++) {
            float* dst = &sp[0][j * PLANE + soff];
            dst[0] = pre[j].x; dst[1] = pre[j].y; dst[2] = pre[j].z; dst[3] = pre[j].w;
        }
        __syncthreads();   // buffer 0 + Ash visible

#pragma unroll
        for (int ph = 0; ph < 4; ph++) {
            int cur = ph & 1;

            // prefetch next phase while computing current
            if (ph < 3) {
                const float4* src = (const float4*)(sbase + (ph + 1) * 4096);
#pragma unroll
                for (int j = 0; j < 4; j++)
                    pre[j] = __ldcs(src + tid + j * 256);
            }

#pragma unroll
            for (int nn = 0; nn < 4; nn++) {
                int n = ph * 4 + nn;
                float4 bvn, cvn;
                if (n < 15) {
                    bvn = *(const float4*)&Bvb[(size_t)(n + 1) << 10];
                    cvn = *(const float4*)&Cvb[(size_t)(n + 1) << 10];
                }
                const float* pl = &sp[cur][nn * PLANE];
                float A_n = Ash[n];
                float bva[4] = {bvc.x, bvc.y, bvc.z, bvc.w};
                float cva[4] = {cvc.x, cvc.y, cvc.z, cvc.w};
                float sn[4];
#pragma unroll
                for (int i = 0; i < 4; i++) {
                    float st;
                    if (single[i]) {
                        st = wt[i].x * pl[it[i].x];
                    } else {
                        st = wt[i].x * pl[it[i].x] + wt[i].y * pl[it[i].y]
                           + wt[i].z * pl[it[i].z] + wt[i].w * pl[it[i].w];
                    }
                    float ab = __expf(dl[i] * A_n);
                    sn[i] = fmaf(ab, st, du[i] * bva[i]);
                    yacc[i] = fmaf(sn[i], cva[i], yacc[i]);
                }
                float4 so = make_float4(sn[0], sn[1], sn[2], sn[3]);
                __stcs((float4*)&snb[((size_t)n << 10) + p0], so);
                if (n < 15) { bvc = bvn; cvc = cvn; }
            }

            // stage next phase into the other buffer
            if (ph < 3) {
#pragma unroll
                for (int j = 0; j < 4; j++) {
                    float* dst = &sp[cur ^ 1][j * PLANE + soff];
                    dst[0] = pre[j].x; dst[1] = pre[j].y; dst[2] = pre[j].z; dst[3] = pre[j].w;
                }
                __syncthreads();   // next buffer visible for phase ph+1
            }
        }
    }

    float Dd = __ldg(&Dp[d]);
    float4 yo = make_float4(fmaf(u4.x, Dd, yacc[0]),
                            fmaf(u4.y, Dd, yacc[1]),
                            fmaf(u4.z, Dd, yacc[2]),
                            fmaf(u4.w, Dd, yacc[3]));
    *(float4*)&y_out[((size_t)blk << 10) + p0] = yo;
}

// ---------------------------------------------------------------------------
// Launch
// ---------------------------------------------------------------------------
extern "C" void kernel_launch(void* const* d_in, const int* in_sizes, int n_in,
                              void* d_out, int out_size) {
    const float* u_t      = (const float*)d_in[0];
    const float* s_prev   = (const float*)d_in[1];
    const float* gn_w     = (const float*)d_in[2];
    const float* gn_b     = (const float*)d_in[3];
    const float* cdw      = (const float*)d_in[4];
    const float* cdb      = (const float*)d_in[5];
    const float* cBw      = (const float*)d_in[6];
    const float* cCw      = (const float*)d_in[7];
    const float* logA     = (const float*)d_in[8];
    const float* D_param  = (const float*)d_in[9];
    const float* dt_bias  = (const float*)d_in[10];

    float* y_out = (float*)d_out;                              // (B,V,D,H,W)
    float* s_out = (float*)d_out + (size_t)B_ * V_ * D_ * HW;  // (B,V,D,N,H,W)

    k_stats_init<<<24, 1024>>>(u_t, logA);
    k_conv<<<B_ * 24 * 4, 256>>>(cdw, cdb, cBw, cCw, u_t, gn_w, gn_b, dt_bias);
    k_main<<<B_ * V_ * D_, 256>>>(s_prev, u_t, D_param, y_out, s_out);
}

// round 15
// speedup vs baseline: 1.0344x; 1.0344x over previous
#include <cuda_runtime.h>
#include <math.h>

// ---------------------------------------------------------------------------
// Problem constants
// ---------------------------------------------------------------------------
#define B_ 4
#define V_ 8
#define D_ 64
#define N_ 16
#define H_ 32
#define W_ 32
#define HW 1024
#define EPS 1e-5f

// smem plane geometry for the gather: row stride 34 -> bank = (2y+x) % 32,
// conflict-free along the +-45 deg tap diagonals.
#define RSTRIDE 34
#define PLANE   (32 * RSTRIDE)   // 1088 floats

// ---------------------------------------------------------------------------
// PDL (programmatic dependent launch) helpers
// ---------------------------------------------------------------------------
__device__ __forceinline__ void pdl_trigger() {
    asm volatile("griddepcontrol.launch_dependents;");
}
__device__ __forceinline__ void pdl_wait() {
    asm volatile("griddepcontrol.wait;" ::: "memory");
}

// ---------------------------------------------------------------------------
// Packed f32x2 helpers (FFMA2 path)
// ---------------------------------------------------------------------------
__device__ __forceinline__ unsigned long long pack2(float x, float y) {
    unsigned long long r;
    asm("mov.b64 %0, {%1, %2};" : "=l"(r) : "f"(x), "f"(y));
    return r;
}
__device__ __forceinline__ void unpack2(unsigned long long p, float& x, float& y) {
    asm("mov.b64 {%0, %1}, %2;" : "=f"(x), "=f"(y) : "l"(p));
}
__device__ __forceinline__ void ffma2(unsigned long long& d,
                                      unsigned long long a, unsigned long long b) {
    asm("fma.rn.f32x2 %0, %1, %2, %0;" : "+l"(d) : "l"(a), "l"(b));
}

// ---------------------------------------------------------------------------
// Scratch (device globals; no dynamic allocation allowed)
// ---------------------------------------------------------------------------
__device__ float  g_delta[B_ * D_ * HW];   // clipped softplus delta
__device__ float  g_du   [B_ * D_ * HW];   // delta * u_t
__device__ float  g_Bv   [B_ * N_ * HW];   // conv_B(u_norm)
__device__ float  g_Cv   [B_ * N_ * HW];   // conv_C(u_norm)
__device__ float  g_A    [D_ * N_];        // -exp(log_A_real)
__device__ float2 g_stat [B_ * 4];         // per (b, group): (mu, rsqrt)
__device__ float4 g_wtab [V_ * HW];        // bilinear weights (masked)
__device__ short4 g_itab [V_ * HW];        // padded-smem tap offsets (stride 34)

// ---------------------------------------------------------------------------
// Kernel 0: fused GN-stats (blocks 0..15) + init tables (blocks 16..23)
// ---------------------------------------------------------------------------
__global__ __launch_bounds__(1024)
void k_stats_init(const float* __restrict__ u, const float* __restrict__ log_A_real) {
    pdl_trigger();   // let conv launch & run its independent prologue

    int blk = blockIdx.x;
    int tid = threadIdx.x;

    if (blk < 16) {
        const float4* base = (const float4*)(u + ((size_t)blk << 14));
        float s = 0.f, ss = 0.f;
#pragma unroll
        for (int it = 0; it < 4; it++) {
            float4 v = base[tid + it * 1024];
            s += v.x + v.y + v.z + v.w;
            ss = fmaf(v.x, v.x, ss);
            ss = fmaf(v.y, v.y, ss);
            ss = fmaf(v.z, v.z, ss);
            ss = fmaf(v.w, v.w, ss);
        }
        for (int o = 16; o; o >>= 1) {
            s  += __shfl_down_sync(0xffffffffu, s, o);
            ss += __shfl_down_sync(0xffffffffu, ss, o);
        }
        __shared__ float shs[32], shss[32];
        int wid = tid >> 5, lid = tid & 31;
        if (lid == 0) { shs[wid] = s; shss[wid] = ss; }
        __syncthreads();
        if (tid == 0) {
            float S = 0.f, SS = 0.f;
#pragma unroll
            for (int i = 0; i < 32; i++) { S += shs[i]; SS += shss[i]; }
            float mu  = S / 16384.0f;
            float var = SS / 16384.0f - mu * mu;
            g_stat[blk] = make_float2(mu, rsqrtf(var + EPS));
        }
        return;
    }

    int gid = (blk - 16) * 1024 + tid;      // 0..8191 ; one v per block
    if (gid < D_ * N_) {
        g_A[gid] = -expf(log_A_real[gid]);
    }

    {
        int v = gid >> 10;
        int p = gid & 1023;
        int h = p >> 5, w = p & 31;

        float c, sn;
        if ((v & 1) == 0) {
            int q = v >> 1;
            c  = (q == 0) ? 1.f : (q == 2) ? -1.f : 0.f;
            sn = (q == 1) ? -1.f : (q == 3) ? 1.f : 0.f;
        } else {
            float ang = (float)v * -0.78539816339744830961f;
            c  = cosf(ang);
            sn = sinf(ang);
        }

        float X = ((w + 0.5f) * 2.0f) / 32.0f - 1.0f;
        float Y = ((h + 0.5f) * 2.0f) / 32.0f - 1.0f;
        float gx = c * X - sn * Y;
        float gy = sn * X + c * Y;
        float ix = (gx + 1.0f) * 16.0f - 0.5f;
        float iy = (gy + 1.0f) * 16.0f - 0.5f;

        float x0f = floorf(ix), y0f = floorf(iy);
        float wx1 = ix - x0f, wy1 = iy - y0f;
        float wx0 = 1.0f - wx1, wy0 = 1.0f - wy1;
        int x0 = (int)x0f, y0 = (int)y0f;
        int x1 = x0 + 1, y1 = y0 + 1;

        auto ok = [](int yy, int xx) { return yy >= 0 && yy < H_ && xx >= 0 && xx < W_; };
        float w00 = ok(y0, x0) ? wy0 * wx0 : 0.0f;
        float w01 = ok(y0, x1) ? wy0 * wx1 : 0.0f;
        float w10 = ok(y1, x0) ? wy1 * wx0 : 0.0f;
        float w11 = ok(y1, x1) ? wy1 * wx1 : 0.0f;

        auto cl = [](int v_, int hi) { return v_ < 0 ? 0 : (v_ > hi ? hi : v_); };
        int y0c = cl(y0, H_ - 1), y1c = cl(y1, H_ - 1);
        int x0c = cl(x0, W_ - 1), x1c = cl(x1, W_ - 1);
        short i00 = (short)(y0c * RSTRIDE + x0c);
        short i01 = (short)(y0c * RSTRIDE + x1c);
        short i10 = (short)(y1c * RSTRIDE + x0c);
        short i11 = (short)(y1c * RSTRIDE + x1c);

        g_wtab[gid] = make_float4(w00, w01, w10, w11);
        g_itab[gid] = make_short4(i00, i01, i10, i11);
    }
}

// ---------------------------------------------------------------------------
// Kernel 1: fused 3x3 convs + inline group-norm, software-pipelined staging.
// PDL: weight + u_t loads issue BEFORE the wait on k_stats_init (only the
// g_stat read is dependent).
// ---------------------------------------------------------------------------
__global__ __launch_bounds__(256)
void k_conv(const float* __restrict__ wD, const float* __restrict__ bD,
            const float* __restrict__ wB, const float* __restrict__ wC,
            const float* __restrict__ u_t,
            const float* __restrict__ gw, const float* __restrict__ gb,
            const float* __restrict__ dt_bias_p) {
    pdl_trigger();   // let main launch & stage s_prev

    int strip = blockIdx.x & 3;
    int rest  = blockIdx.x >> 2;
    int ocq   = rest % 24;
    int b     = rest / 24;
    int tid   = threadIdx.x;

    __shared__ __align__(16) float wsh[D_ * 9 * 4];  // [ic][tap][j]  9216 B
    __shared__ float buf[2][2][340];                 // 5440 B
    __shared__ float ssc[64], ssh[64];               // per-ic normalize

    // --- independent prologue: weights + first u_t loads ---
    for (int k = tid; k < D_ * 9 * 4; k += 256) {
        int j   = k & 3;
        int tap = (k >> 2) % 9;
        int ic  = k / 36;
        int oc  = ocq * 4 + j;
        const float* src;
        if (oc < 64)      src = wD + (size_t)oc * 576;
        else if (oc < 80) src = wB + (size_t)(oc - 64) * 576;
        else              src = wC + (size_t)(oc - 80) * 576;
        wsh[k] = src[ic * 9 + tap];
    }

    int h0    = strip * 8;
    int local = tid >> 5;    // 0..7
    int col   = tid & 31;

    int r1 = tid / 34, c1 = tid - r1 * 34;
    int gr1 = h0 - 1 + r1, gc1 = c1 - 1;
    bool ok1 = (gr1 >= 0) && (gr1 < 32) && (gc1 >= 0) && (gc1 < 32);
    int go1 = ok1 ? gr1 * 32 + gc1 : 0;
    int k2 = tid + 256;
    bool has2 = (k2 < 340);
    int r2 = k2 / 34, c2 = k2 - r2 * 34;
    int gr2 = h0 - 1 + r2, gc2 = c2 - 1;
    bool ok2 = has2 && (gr2 >= 0) && (gr2 < 32) && (gc2 >= 0) && (gc2 < 32);
    int go2 = ok2 ? gr2 * 32 + gc2 : 0;

    const float* ubase = u_t + ((size_t)b << 16);

    float ra0 = ok1 ? __ldg(ubase + go1)        : 0.f;
    float ra1 = ok1 ? __ldg(ubase + 1024 + go1) : 0.f;
    float rb0 = ok2 ? __ldg(ubase + go2)        : 0.f;
    float rb1 = ok2 ? __ldg(ubase + 1024 + go2) : 0.f;

    // --- dependent part starts here ---
    pdl_wait();

    if (tid < 64) {
        float2 st = g_stat[b * 4 + (tid >> 4)];
        float sc = st.y * gw[tid];
        ssc[tid] = sc;
        ssh[tid] = gb[tid] - st.x * sc;
    }

    unsigned long long acc01 = 0ULL, acc23 = 0ULL;

    __syncthreads();   // wsh + ssc/ssh visible

    buf[0][0][tid] = ok1 ? fmaf(ra0, ssc[0], ssh[0]) : 0.f;
    buf[0][1][tid] = ok1 ? fmaf(ra1, ssc[1], ssh[1]) : 0.f;
    if (has2) {
        buf[0][0][k2] = ok2 ? fmaf(rb0, ssc[0], ssh[0]) : 0.f;
        buf[0][1][k2] = ok2 ? fmaf(rb1, ssc[1], ssh[1]) : 0.f;
    }
    __syncthreads();

    for (int pair = 0; pair < 32; pair++) {
        int cur = pair & 1;
        int nxt = cur ^ 1;
        int icn0 = pair * 2 + 2;

        if (pair < 31) {
            const float* u0 = ubase + ((size_t)icn0 << 10);
            ra0 = ok1 ? __ldg(u0 + go1)        : 0.f;
            ra1 = ok1 ? __ldg(u0 + 1024 + go1) : 0.f;
            rb0 = ok2 ? __ldg(u0 + go2)        : 0.f;
            rb1 = ok2 ? __ldg(u0 + 1024 + go2) : 0.f;
        }

#pragma unroll
        for (int ii = 0; ii < 2; ii++) {
            int ic = pair * 2 + ii;
            const float* pb = buf[cur][ii];
            const float* wp = &wsh[ic * 36];
#pragma unroll
            for (int r = 0; r < 3; r++) {
#pragma unroll
                for (int c = 0; c < 3; c++) {
                    float t = pb[(local + r) * 34 + col + c];
                    unsigned long long tt = pack2(t, t);
                    ulonglong2 wv = *(const ulonglong2*)&wp[(r * 3 + c) * 4];
                    ffma2(acc01, tt, wv.x);
                    ffma2(acc23, tt, wv.y);
                }
            }
        }

        if (pair < 31) {
            buf[nxt][0][tid] = ok1 ? fmaf(ra0, ssc[icn0],     ssh[icn0])     : 0.f;
            buf[nxt][1][tid] = ok1 ? fmaf(ra1, ssc[icn0 + 1], ssh[icn0 + 1]) : 0.f;
            if (has2) {
                buf[nxt][0][k2] = ok2 ? fmaf(rb0, ssc[icn0],     ssh[icn0])     : 0.f;
                buf[nxt][1][k2] = ok2 ? fmaf(rb1, ssc[icn0 + 1], ssh[icn0 + 1]) : 0.f;
            }
        }
        __syncthreads();
    }

    float acc[4];
    unpack2(acc01, acc[0], acc[1]);
    unpack2(acc23, acc[2], acc[3]);

    int p = (h0 + local) * 32 + col;
    if (ocq < 16) {
        float dtb = dt_bias_p[0];
#pragma unroll
        for (int j = 0; j < 4; j++) {
            int oc = ocq * 4 + j;
            float x  = acc[j] + bD[oc] + dtb;
            float sp = fmaxf(x, 0.0f) + log1pf(expf(-fabsf(x)));
            float d  = fminf(fmaxf(sp, 1e-4f), 5.0f);
            size_t idx = ((size_t)(b * D_ + oc) << 10) + p;
            g_delta[idx] = d;
            g_du[idx]    = d * u_t[idx];
        }
    } else if (ocq < 20) {
#pragma unroll
        for (int j = 0; j < 4; j++) {
            int n = (ocq - 16) * 4 + j;
            g_Bv[((size_t)(b * N_ + n) << 10) + p] = acc[j];
        }
    } else {
#pragma unroll
        for (int j = 0; j < 4; j++) {
            int n = (ocq - 20) * 4 + j;
            g_Cv[((size_t)(b * N_ + n) << 10) + p] = acc[j];
        }
    }
}

// ---------------------------------------------------------------------------
// Kernel 2: main transport + SSM update + einsum
// PDL: s_prev phase-0 staging issues BEFORE the wait on k_conv; all
// conv/stats-dependent loads after.
// ---------------------------------------------------------------------------
__global__ __launch_bounds__(256)
void k_main(const float* __restrict__ s_prev,
            const float* __restrict__ u_t,
            const float* __restrict__ Dp,
            float* __restrict__ y_out,
            float* __restrict__ s_out) {
    int blk = blockIdx.x;                 // = ((b*V + v)*D + d)
    int d = blk & 63;
    int v = (blk >> 6) & 7;
    int b = blk >> 9;

    __shared__ float sp[2][4 * PLANE];    // 34816 B (double-buffered)
    __shared__ float Ash[N_];

    int tid = threadIdx.x;
    int p0  = tid * 4;

    const float* sbase = s_prev + ((size_t)blk << 14);
    float*       snb   = s_out  + ((size_t)blk << 14);
    const float* Bvb   = g_Bv + ((size_t)b << 14) + p0;
    const float* Cvb   = g_Cv + ((size_t)b << 14) + p0;
    size_t bdp = ((size_t)(b * D_ + d) << 10) + p0;

    float yacc[4] = {0.f, 0.f, 0.f, 0.f};

    if (v == 0 || v == 4) {
        bool mir = (v == 4);
        int fidx = mir ? (255 - tid) : tid;

        // independent prologue: first group's s planes
        float4 sv[4];
#pragma unroll
        for (int j = 0; j < 4; j++)
            sv[j] = __ldcs((const float4*)(sbase + ((size_t)j << 10)) + fidx);

        pdl_wait();

        float4 dl4 = *(const float4*)&g_delta[bdp];
        float4 du4 = *(const float4*)&g_du[bdp];
        float4 u4  = *(const float4*)&u_t[bdp];
        float dl[4] = {dl4.x, dl4.y, dl4.z, dl4.w};
        float du[4] = {du4.x, du4.y, du4.z, du4.w};

#pragma unroll
        for (int g = 0; g < 4; g++) {
            float4 svn[4];
            if (g < 3) {
#pragma unroll
                for (int j = 0; j < 4; j++)
                    svn[j] = __ldcs((const float4*)(sbase + ((size_t)((g + 1) * 4 + j) << 10)) + fidx);
            }
#pragma unroll
            for (int j = 0; j < 4; j++) {
                int n = g * 4 + j;
                float A_n = __ldg(&g_A[d * N_ + n]);
                float4 bv = *(const float4*)&Bvb[(size_t)n << 10];
                float4 cv = *(const float4*)&Cvb[(size_t)n << 10];
                float stv[4];
                if (mir) {
                    stv[0] = sv[j].w; stv[1] = sv[j].z; stv[2] = sv[j].y; stv[3] = sv[j].x;
                } else {
                    stv[0] = sv[j].x; stv[1] = sv[j].y; stv[2] = sv[j].z; stv[3] = sv[j].w;
                }
                float bva[4] = {bv.x, bv.y, bv.z, bv.w};
                float cva[4] = {cv.x, cv.y, cv.z, cv.w};
                float sn[4];
#pragma unroll
                for (int i = 0; i < 4; i++) {
                    float ab = __expf(dl[i] * A_n);
                    sn[i] = fmaf(ab, stv[i], du[i] * bva[i]);
                    yacc[i] = fmaf(sn[i], cva[i], yacc[i]);
                }
                float4 so = make_float4(sn[0], sn[1], sn[2], sn[3]);
                __stcs((float4*)&snb[((size_t)n << 10) + p0], so);
            }
            if (g < 3) {
#pragma unroll
                for (int j = 0; j < 4; j++) sv[j] = svn[j];
            }
        }

        float Dd = __ldg(&Dp[d]);
        float4 yo = make_float4(fmaf(u4.x, Dd, yacc[0]),
                                fmaf(u4.y, Dd, yacc[1]),
                                fmaf(u4.z, Dd, yacc[2]),
                                fmaf(u4.w, Dd, yacc[3]));
        *(float4*)&y_out[((size_t)blk << 10) + p0] = yo;
    } else {
        int soff = (p0 >> 5) * RSTRIDE + (p0 & 31);

        // independent prologue: load + stage phase 0 into buffer 0
        float4 pre[4];
#pragma unroll
        for (int j = 0; j < 4; j++)
            pre[j] = __ldcs((const float4*)sbase + tid + j * 256);
#pragma unroll
        for (int j = 0; j < 4; j++) {
            float* dst = &sp[0][j * PLANE + soff];
            dst[0] = pre[j].x; dst[1] = pre[j].y; dst[2] = pre[j].z; dst[3] = pre[j].w;
        }

        pdl_wait();

        // dependent loads
        float4 dl4 = *(const float4*)&g_delta[bdp];
        float4 du4 = *(const float4*)&g_du[bdp];
        float4 u4  = *(const float4*)&u_t[bdp];
        float dl[4] = {dl4.x, dl4.y, dl4.z, dl4.w};
        float du[4] = {du4.x, du4.y, du4.z, du4.w};

        if (tid < N_) Ash[tid] = g_A[d * N_ + tid];

        float4 wt[4];
        short4 it[4];
        bool   single[4];
#pragma unroll
        for (int i = 0; i < 4; i++) {
            int tabi = (v << 10) + p0 + i;
            wt[i] = g_wtab[tabi];
            it[i] = g_itab[tabi];
            single[i] = (wt[i].y == 0.0f) && (wt[i].z == 0.0f) && (wt[i].w == 0.0f);
        }

        __syncthreads();   // buffer 0 + Ash visible

#pragma unroll
        for (int ph = 0; ph < 4; ph++) {
            int cur = ph & 1;

            if (ph < 3) {
                const float4* src = (const float4*)(sbase + (ph + 1) * 4096);
#pragma unroll
                for (int j = 0; j < 4; j++)
                    pre[j] = __ldcs(src + tid + j * 256);
            }

#pragma unroll
            for (int nn = 0; nn < 4; nn++) {
                int n = ph * 4 + nn;
                const float* pl = &sp[cur][nn * PLANE];
                float A_n = Ash[n];
                float4 bv = *(const float4*)&Bvb[(size_t)n << 10];
                float4 cv = *(const float4*)&Cvb[(size_t)n << 10];
                float bva[4] = {bv.x, bv.y, bv.z, bv.w};
                float cva[4] = {cv.x, cv.y, cv.z, cv.w};
                float sn[4];
#pragma unroll
                for (int i = 0; i < 4; i++) {
                    float st;
                    if (single[i]) {
                        st = wt[i].x * pl[it[i].x];
                    } else {
                        st = wt[i].x * pl[it[i].x] + wt[i].y * pl[it[i].y]
                           + wt[i].z * pl[it[i].z] + wt[i].w * pl[it[i].w];
                    }
                    float ab = __expf(dl[i] * A_n);
                    sn[i] = fmaf(ab, st, du[i] * bva[i]);
                    yacc[i] = fmaf(sn[i], cva[i], yacc[i]);
                }
                float4 so = make_float4(sn[0], sn[1], sn[2], sn[3]);
                __stcs((float4*)&snb[((size_t)n << 10) + p0], so);
            }

            if (ph < 3) {
#pragma unroll
                for (int j = 0; j < 4; j++) {
                    float* dst = &sp[cur ^ 1][j * PLANE + soff];
                    dst[0] = pre[j].x; dst[1] = pre[j].y; dst[2] = pre[j].z; dst[3] = pre[j].w;
                }
                __syncthreads();
            }
        }

        float Dd = __ldg(&Dp[d]);
        float4 yo = make_float4(fmaf(u4.x, Dd, yacc[0]),
                                fmaf(u4.y, Dd, yacc[1]),
                                fmaf(u4.z, Dd, yacc[2]),
                                fmaf(u4.w, Dd, yacc[3]));
        *(float4*)&y_out[((size_t)blk << 10) + p0] = yo;
    }
}

// ---------------------------------------------------------------------------
// Launch: stats normal; conv + main via cudaLaunchKernelEx with PDL attr
// ---------------------------------------------------------------------------
extern "C" void kernel_launch(void* const* d_in, const int* in_sizes, int n_in,
                              void* d_out, int out_size) {
    const float* u_t      = (const float*)d_in[0];
    const float* s_prev   = (const float*)d_in[1];
    const float* gn_w     = (const float*)d_in[2];
    const float* gn_b     = (const float*)d_in[3];
    const float* cdw      = (const float*)d_in[4];
    const float* cdb      = (const float*)d_in[5];
    const float* cBw      = (const float*)d_in[6];
    const float* cCw      = (const float*)d_in[7];
    const float* logA     = (const float*)d_in[8];
    const float* D_param  = (const float*)d_in[9];
    const float* dt_bias  = (const float*)d_in[10];

    float* y_out = (float*)d_out;                              // (B,V,D,H,W)
    float* s_out = (float*)d_out + (size_t)B_ * V_ * D_ * HW;  // (B,V,D,N,H,W)

    k_stats_init<<<24, 1024>>>(u_t, logA);

    cudaLaunchAttribute attrs[1];
    attrs[0].id = cudaLaunchAttributeProgrammaticStreamSerialization;
    attrs[0].val.programmaticStreamSerializationAllowed = 1;

    {
        cudaLaunchConfig_t cfg = {};
        cfg.gridDim  = dim3(B_ * 24 * 4, 1, 1);
        cfg.blockDim = dim3(256, 1, 1);
        cfg.dynamicSmemBytes = 0;
        cfg.stream = 0;
        cfg.attrs = attrs;
        cfg.numAttrs = 1;
        cudaLaunchKernelEx(&cfg, k_conv, cdw, cdb, cBw, cCw, u_t, gn_w, gn_b, dt_bias);
    }
    {
        cudaLaunchConfig_t cfg = {};
        cfg.gridDim  = dim3(B_ * V_ * D_, 1, 1);
        cfg.blockDim = dim3(256, 1, 1);
        cfg.dynamicSmemBytes = 0;
        cfg.stream = 0;
        cfg.attrs = attrs;
        cfg.numAttrs = 1;
        cudaLaunchKernelEx(&cfg, k_main, s_prev, u_t, D_param, y_out, s_out);
    }
}

// round 17
// speedup vs baseline: 1.0674x; 1.0320x over previous
#include <cuda_runtime.h>
#include <math.h>
#include <stdint.h>

// ---------------------------------------------------------------------------
// Problem constants
// ---------------------------------------------------------------------------
#define B_ 4
#define V_ 8
#define D_ 64
#define N_ 16
#define H_ 32
#define W_ 32
#define HW 1024
#define EPS 1e-5f

// smem plane geometry: row stride 36 (16B-aligned rows for cp.async).
// Banks: diagonal taps step +-36+-1 = {3,5} mod 32 -> conflict-free;
// vertical taps (v=2,6) 4-way conflicted but issue 4x fewer LDS -> neutral.
#define RSTRIDE 36
#define PLANE   (32 * RSTRIDE)   // 1152 floats

// ---------------------------------------------------------------------------
// PDL helpers
// ---------------------------------------------------------------------------
__device__ __forceinline__ void pdl_trigger() {
    asm volatile("griddepcontrol.launch_dependents;");
}
__device__ __forceinline__ void pdl_wait() {
    asm volatile("griddepcontrol.wait;" ::: "memory");
}

// ---------------------------------------------------------------------------
// cp.async helpers (16B, L1-bypass .cg path)
// ---------------------------------------------------------------------------
__device__ __forceinline__ uint32_t smem_u32(const void* p) {
    uint32_t a;
    asm("{ .reg .u64 t; cvta.to.shared.u64 t, %1; cvt.u32.u64 %0, t; }"
        : "=r"(a) : "l"(p));
    return a;
}
#define CP_ASYNC16(dst_u32, src_ptr) \
    asm volatile("cp.async.cg.shared.global [%0], [%1], 16;" \
                 :: "r"(dst_u32), "l"(src_ptr) : "memory")
#define CP_COMMIT() asm volatile("cp.async.commit_group;" ::: "memory")
#define CP_WAIT0()  asm volatile("cp.async.wait_group 0;" ::: "memory")

// ---------------------------------------------------------------------------
// Packed f32x2 helpers (FFMA2 path)
// ---------------------------------------------------------------------------
__device__ __forceinline__ unsigned long long pack2(float x, float y) {
    unsigned long long r;
    asm("mov.b64 %0, {%1, %2};" : "=l"(r) : "f"(x), "f"(y));
    return r;
}
__device__ __forceinline__ void unpack2(unsigned long long p, float& x, float& y) {
    asm("mov.b64 {%0, %1}, %2;" : "=f"(x), "=f"(y) : "l"(p));
}
__device__ __forceinline__ void ffma2(unsigned long long& d,
                                      unsigned long long a, unsigned long long b) {
    asm("fma.rn.f32x2 %0, %1, %2, %0;" : "+l"(d) : "l"(a), "l"(b));
}

// ---------------------------------------------------------------------------
// Scratch
// ---------------------------------------------------------------------------
__device__ float  g_delta[B_ * D_ * HW];
__device__ float  g_du   [B_ * D_ * HW];
__device__ float  g_Bv   [B_ * N_ * HW];
__device__ float  g_Cv   [B_ * N_ * HW];
__device__ float  g_A    [D_ * N_];
__device__ float2 g_stat [B_ * 4];
__device__ float4 g_wtab [V_ * HW];
__device__ short4 g_itab [V_ * HW];      // tap offsets (stride 36)

// ---------------------------------------------------------------------------
// Kernel 0: fused GN-stats (blocks 0..15) + init tables (blocks 16..23)
// ---------------------------------------------------------------------------
__global__ __launch_bounds__(1024)
void k_stats_init(const float* __restrict__ u, const float* __restrict__ log_A_real) {
    pdl_trigger();

    int blk = blockIdx.x;
    int tid = threadIdx.x;

    if (blk < 16) {
        const float4* base = (const float4*)(u + ((size_t)blk << 14));
        float s = 0.f, ss = 0.f;
#pragma unroll
        for (int it = 0; it < 4; it++) {
            float4 v = base[tid + it * 1024];
            s += v.x + v.y + v.z + v.w;
            ss = fmaf(v.x, v.x, ss);
            ss = fmaf(v.y, v.y, ss);
            ss = fmaf(v.z, v.z, ss);
            ss = fmaf(v.w, v.w, ss);
        }
        for (int o = 16; o; o >>= 1) {
            s  += __shfl_down_sync(0xffffffffu, s, o);
            ss += __shfl_down_sync(0xffffffffu, ss, o);
        }
        __shared__ float shs[32], shss[32];
        int wid = tid >> 5, lid = tid & 31;
        if (lid == 0) { shs[wid] = s; shss[wid] = ss; }
        __syncthreads();
        if (tid == 0) {
            float S = 0.f, SS = 0.f;
#pragma unroll
            for (int i = 0; i < 32; i++) { S += shs[i]; SS += shss[i]; }
            float mu  = S / 16384.0f;
            float var = SS / 16384.0f - mu * mu;
            g_stat[blk] = make_float2(mu, rsqrtf(var + EPS));
        }
        return;
    }

    int gid = (blk - 16) * 1024 + tid;
    if (gid < D_ * N_) {
        g_A[gid] = -expf(log_A_real[gid]);
    }

    {
        int v = gid >> 10;
        int p = gid & 1023;
        int h = p >> 5, w = p & 31;

        float c, sn;
        if ((v & 1) == 0) {
            int q = v >> 1;
            c  = (q == 0) ? 1.f : (q == 2) ? -1.f : 0.f;
            sn = (q == 1) ? -1.f : (q == 3) ? 1.f : 0.f;
        } else {
            float ang = (float)v * -0.78539816339744830961f;
            c  = cosf(ang);
            sn = sinf(ang);
        }

        float X = ((w + 0.5f) * 2.0f) / 32.0f - 1.0f;
        float Y = ((h + 0.5f) * 2.0f) / 32.0f - 1.0f;
        float gx = c * X - sn * Y;
        float gy = sn * X + c * Y;
        float ix = (gx + 1.0f) * 16.0f - 0.5f;
        float iy = (gy + 1.0f) * 16.0f - 0.5f;

        float x0f = floorf(ix), y0f = floorf(iy);
        float wx1 = ix - x0f, wy1 = iy - y0f;
        float wx0 = 1.0f - wx1, wy0 = 1.0f - wy1;
        int x0 = (int)x0f, y0 = (int)y0f;
        int x1 = x0 + 1, y1 = y0 + 1;

        auto ok = [](int yy, int xx) { return yy >= 0 && yy < H_ && xx >= 0 && xx < W_; };
        float w00 = ok(y0, x0) ? wy0 * wx0 : 0.0f;
        float w01 = ok(y0, x1) ? wy0 * wx1 : 0.0f;
        float w10 = ok(y1, x0) ? wy1 * wx0 : 0.0f;
        float w11 = ok(y1, x1) ? wy1 * wx1 : 0.0f;

        auto cl = [](int v_, int hi) { return v_ < 0 ? 0 : (v_ > hi ? hi : v_); };
        int y0c = cl(y0, H_ - 1), y1c = cl(y1, H_ - 1);
        int x0c = cl(x0, W_ - 1), x1c = cl(x1, W_ - 1);
        short i00 = (short)(y0c * RSTRIDE + x0c);
        short i01 = (short)(y0c * RSTRIDE + x1c);
        short i10 = (short)(y1c * RSTRIDE + x0c);
        short i11 = (short)(y1c * RSTRIDE + x1c);

        g_wtab[gid] = make_float4(w00, w01, w10, w11);
        g_itab[gid] = make_short4(i00, i01, i10, i11);
    }
}

// ---------------------------------------------------------------------------
// Kernel 1: fused 3x3 convs + inline group-norm (unchanged from R15)
// ---------------------------------------------------------------------------
__global__ __launch_bounds__(256)
void k_conv(const float* __restrict__ wD, const float* __restrict__ bD,
            const float* __restrict__ wB, const float* __restrict__ wC,
            const float* __restrict__ u_t,
            const float* __restrict__ gw, const float* __restrict__ gb,
            const float* __restrict__ dt_bias_p) {
    pdl_trigger();

    int strip = blockIdx.x & 3;
    int rest  = blockIdx.x >> 2;
    int ocq   = rest % 24;
    int b     = rest / 24;
    int tid   = threadIdx.x;

    __shared__ __align__(16) float wsh[D_ * 9 * 4];
    __shared__ float buf[2][2][340];
    __shared__ float ssc[64], ssh[64];

    for (int k = tid; k < D_ * 9 * 4; k += 256) {
        int j   = k & 3;
        int tap = (k >> 2) % 9;
        int ic  = k / 36;
        int oc  = ocq * 4 + j;
        const float* src;
        if (oc < 64)      src = wD + (size_t)oc * 576;
        else if (oc < 80) src = wB + (size_t)(oc - 64) * 576;
        else              src = wC + (size_t)(oc - 80) * 576;
        wsh[k] = src[ic * 9 + tap];
    }

    int h0    = strip * 8;
    int local = tid >> 5;
    int col   = tid & 31;

    int r1 = tid / 34, c1 = tid - r1 * 34;
    int gr1 = h0 - 1 + r1, gc1 = c1 - 1;
    bool ok1 = (gr1 >= 0) && (gr1 < 32) && (gc1 >= 0) && (gc1 < 32);
    int go1 = ok1 ? gr1 * 32 + gc1 : 0;
    int k2 = tid + 256;
    bool has2 = (k2 < 340);
    int r2 = k2 / 34, c2 = k2 - r2 * 34;
    int gr2 = h0 - 1 + r2, gc2 = c2 - 1;
    bool ok2 = has2 && (gr2 >= 0) && (gr2 < 32) && (gc2 >= 0) && (gc2 < 32);
    int go2 = ok2 ? gr2 * 32 + gc2 : 0;

    const float* ubase = u_t + ((size_t)b << 16);

    float ra0 = ok1 ? __ldg(ubase + go1)        : 0.f;
    float ra1 = ok1 ? __ldg(ubase + 1024 + go1) : 0.f;
    float rb0 = ok2 ? __ldg(ubase + go2)        : 0.f;
    float rb1 = ok2 ? __ldg(ubase + 1024 + go2) : 0.f;

    pdl_wait();

    if (tid < 64) {
        float2 st = g_stat[b * 4 + (tid >> 4)];
        float sc = st.y * gw[tid];
        ssc[tid] = sc;
        ssh[tid] = gb[tid] - st.x * sc;
    }

    unsigned long long acc01 = 0ULL, acc23 = 0ULL;

    __syncthreads();

    buf[0][0][tid] = ok1 ? fmaf(ra0, ssc[0], ssh[0]) : 0.f;
    buf[0][1][tid] = ok1 ? fmaf(ra1, ssc[1], ssh[1]) : 0.f;
    if (has2) {
        buf[0][0][k2] = ok2 ? fmaf(rb0, ssc[0], ssh[0]) : 0.f;
        buf[0][1][k2] = ok2 ? fmaf(rb1, ssc[1], ssh[1]) : 0.f;
    }
    __syncthreads();

    for (int pair = 0; pair < 32; pair++) {
        int cur = pair & 1;
        int nxt = cur ^ 1;
        int icn0 = pair * 2 + 2;

        if (pair < 31) {
            const float* u0 = ubase + ((size_t)icn0 << 10);
            ra0 = ok1 ? __ldg(u0 + go1)        : 0.f;
            ra1 = ok1 ? __ldg(u0 + 1024 + go1) : 0.f;
            rb0 = ok2 ? __ldg(u0 + go2)        : 0.f;
            rb1 = ok2 ? __ldg(u0 + 1024 + go2) : 0.f;
        }

#pragma unroll
        for (int ii = 0; ii < 2; ii++) {
            int ic = pair * 2 + ii;
            const float* pb = buf[cur][ii];
            const float* wp = &wsh[ic * 36];
#pragma unroll
            for (int r = 0; r < 3; r++) {
#pragma unroll
                for (int c = 0; c < 3; c++) {
                    float t = pb[(local + r) * 34 + col + c];
                    unsigned long long tt = pack2(t, t);
                    ulonglong2 wv = *(const ulonglong2*)&wp[(r * 3 + c) * 4];
                    ffma2(acc01, tt, wv.x);
                    ffma2(acc23, tt, wv.y);
                }
            }
        }

        if (pair < 31) {
            buf[nxt][0][tid] = ok1 ? fmaf(ra0, ssc[icn0],     ssh[icn0])     : 0.f;
            buf[nxt][1][tid] = ok1 ? fmaf(ra1, ssc[icn0 + 1], ssh[icn0 + 1]) : 0.f;
            if (has2) {
                buf[nxt][0][k2] = ok2 ? fmaf(rb0, ssc[icn0],     ssh[icn0])     : 0.f;
                buf[nxt][1][k2] = ok2 ? fmaf(rb1, ssc[icn0 + 1], ssh[icn0 + 1]) : 0.f;
            }
        }
        __syncthreads();
    }

    float acc[4];
    unpack2(acc01, acc[0], acc[1]);
    unpack2(acc23, acc[2], acc[3]);

    int p = (h0 + local) * 32 + col;
    if (ocq < 16) {
        float dtb = dt_bias_p[0];
#pragma unroll
        for (int j = 0; j < 4; j++) {
            int oc = ocq * 4 + j;
            float x  = acc[j] + bD[oc] + dtb;
            float sp = fmaxf(x, 0.0f) + log1pf(expf(-fabsf(x)));
            float d  = fminf(fmaxf(sp, 1e-4f), 5.0f);
            size_t idx = ((size_t)(b * D_ + oc) << 10) + p;
            g_delta[idx] = d;
            g_du[idx]    = d * u_t[idx];
        }
    } else if (ocq < 20) {
#pragma unroll
        for (int j = 0; j < 4; j++) {
            int n = (ocq - 16) * 4 + j;
            g_Bv[((size_t)(b * N_ + n) << 10) + p] = acc[j];
        }
    } else {
#pragma unroll
        for (int j = 0; j < 4; j++) {
            int n = (ocq - 20) * 4 + j;
            g_Cv[((size_t)(b * N_ + n) << 10) + p] = acc[j];
        }
    }
}

// ---------------------------------------------------------------------------
// Kernel 2: main transport + SSM update + einsum
// Gather path staged via cp.async.cg (16B) into double-buffered stride-36
// smem: removes 512 STS + 128 LDG warp-inst/block and the register buffers.
// ---------------------------------------------------------------------------
__global__ __launch_bounds__(256)
void k_main(const float* __restrict__ s_prev,
            const float* __restrict__ u_t,
            const float* __restrict__ Dp,
            float* __restrict__ y_out,
            float* __restrict__ s_out) {
    int blk = blockIdx.x;                 // = ((b*V + v)*D + d)
    int d = blk & 63;
    int v = (blk >> 6) & 7;
    int b = blk >> 9;

    __shared__ __align__(16) float sp[2][4 * PLANE];   // 36864 B
    __shared__ float Ash[N_];

    int tid = threadIdx.x;
    int p0  = tid * 4;

    const float* sbase = s_prev + ((size_t)blk << 14);
    float*       snb   = s_out  + ((size_t)blk << 14);
    const float* Bvb   = g_Bv + ((size_t)b << 14) + p0;
    const float* Cvb   = g_Cv + ((size_t)b << 14) + p0;
    size_t bdp = ((size_t)(b * D_ + d) << 10) + p0;

    float yacc[4] = {0.f, 0.f, 0.f, 0.f};

    if (v == 0 || v == 4) {
        bool mir = (v == 4);
        int fidx = mir ? (255 - tid) : tid;

        float4 sv[4];
#pragma unroll
        for (int j = 0; j < 4; j++)
            sv[j] = __ldcs((const float4*)(sbase + ((size_t)j << 10)) + fidx);

        pdl_wait();

        float4 dl4 = *(const float4*)&g_delta[bdp];
        float4 du4 = *(const float4*)&g_du[bdp];
        float4 u4  = *(const float4*)&u_t[bdp];
        float dl[4] = {dl4.x, dl4.y, dl4.z, dl4.w};
        float du[4] = {du4.x, du4.y, du4.z, du4.w};

#pragma unroll
        for (int g = 0; g < 4; g++) {
            float4 svn[4];
            if (g < 3) {
#pragma unroll
                for (int j = 0; j < 4; j++)
                    svn[j] = __ldcs((const float4*)(sbase + ((size_t)((g + 1) * 4 + j) << 10)) + fidx);
            }
#pragma unroll
            for (int j = 0; j < 4; j++) {
                int n = g * 4 + j;
                float A_n = __ldg(&g_A[d * N_ + n]);
                float4 bv = *(const float4*)&Bvb[(size_t)n << 10];
                float4 cv = *(const float4*)&Cvb[(size_t)n << 10];
                float stv[4];
                if (mir) {
                    stv[0] = sv[j].w; stv[1] = sv[j].z; stv[2] = sv[j].y; stv[3] = sv[j].x;
                } else {
                    stv[0] = sv[j].x; stv[1] = sv[j].y; stv[2] = sv[j].z; stv[3] = sv[j].w;
                }
                float bva[4] = {bv.x, bv.y, bv.z, bv.w};
                float cva[4] = {cv.x, cv.y, cv.z, cv.w};
                float sn[4];
#pragma unroll
                for (int i = 0; i < 4; i++) {
                    float ab = __expf(dl[i] * A_n);
                    sn[i] = fmaf(ab, stv[i], du[i] * bva[i]);
                    yacc[i] = fmaf(sn[i], cva[i], yacc[i]);
                }
                float4 so = make_float4(sn[0], sn[1], sn[2], sn[3]);
                __stcs((float4*)&snb[((size_t)n << 10) + p0], so);
            }
            if (g < 3) {
#pragma unroll
                for (int j = 0; j < 4; j++) sv[j] = svn[j];
            }
        }

        float Dd = __ldg(&Dp[d]);
        float4 yo = make_float4(fmaf(u4.x, Dd, yacc[0]),
                                fmaf(u4.y, Dd, yacc[1]),
                                fmaf(u4.z, Dd, yacc[2]),
                                fmaf(u4.w, Dd, yacc[3]));
        *(float4*)&y_out[((size_t)blk << 10) + p0] = yo;
    } else {
        int soff = (p0 >> 5) * RSTRIDE + (p0 & 31);   // 16B-aligned slot
        uint32_t spu = smem_u32(&sp[0][0]);
        uint32_t dst_off = (uint32_t)soff * 4u;        // byte offset of slot

        // independent prologue: cp.async phase 0 -> buffer 0
#pragma unroll
        for (int j = 0; j < 4; j++)
            CP_ASYNC16(spu + (uint32_t)(j * PLANE) * 4u + dst_off,
                       sbase + j * 1024 + p0);
        CP_COMMIT();

        pdl_wait();

        float4 dl4 = *(const float4*)&g_delta[bdp];
        float4 du4 = *(const float4*)&g_du[bdp];
        float4 u4  = *(const float4*)&u_t[bdp];
        float dl[4] = {dl4.x, dl4.y, dl4.z, dl4.w};
        float du[4] = {du4.x, du4.y, du4.z, du4.w};

        if (tid < N_) Ash[tid] = g_A[d * N_ + tid];

        float4 wt[4];
        short4 it[4];
        bool   single[4];
#pragma unroll
        for (int i = 0; i < 4; i++) {
            int tabi = (v << 10) + p0 + i;
            wt[i] = g_wtab[tabi];
            it[i] = g_itab[tabi];
            single[i] = (wt[i].y == 0.0f) && (wt[i].z == 0.0f) && (wt[i].w == 0.0f);
        }

#pragma unroll
        for (int ph = 0; ph < 4; ph++) {
            int cur = ph & 1;

            CP_WAIT0();          // buf[cur]'s group complete (this thread)
            __syncthreads();     // all threads' copies visible + prev compute done

            // issue next phase into the other buffer (its readers finished
            // before the barrier above)
            if (ph < 3) {
                const float* src = sbase + (ph + 1) * 4096 + p0;
                uint32_t dbase = spu + (uint32_t)((cur ^ 1) * 4 * PLANE) * 4u + dst_off;
#pragma unroll
                for (int j = 0; j < 4; j++)
                    CP_ASYNC16(dbase + (uint32_t)(j * PLANE) * 4u, src + j * 1024);
                CP_COMMIT();
            }

#pragma unroll
            for (int nn = 0; nn < 4; nn++) {
                int n = ph * 4 + nn;
                const float* pl = &sp[cur][nn * PLANE];
                float A_n = Ash[n];
                float4 bv = *(const float4*)&Bvb[(size_t)n << 10];
                float4 cv = *(const float4*)&Cvb[(size_t)n << 10];
                float bva[4] = {bv.x, bv.y, bv.z, bv.w};
                float cva[4] = {cv.x, cv.y, cv.z, cv.w};
                float sn[4];
#pragma unroll
                for (int i = 0; i < 4; i++) {
                    float st;
                    if (single[i]) {
                        st = wt[i].x * pl[it[i].x];
                    } else {
                        st = wt[i].x * pl[it[i].x] + wt[i].y * pl[it[i].y]
                           + wt[i].z * pl[it[i].z] + wt[i].w * pl[it[i].w];
                    }
                    float ab = __expf(dl[i] * A_n);
                    sn[i] = fmaf(ab, st, du[i] * bva[i]);
                    yacc[i] = fmaf(sn[i], cva[i], yacc[i]);
                }
                float4 so = make_float4(sn[0], sn[1], sn[2], sn[3]);
                __stcs((float4*)&snb[((size_t)n << 10) + p0], so);
            }
        }

        float Dd = __ldg(&Dp[d]);
        float4 yo = make_float4(fmaf(u4.x, Dd, yacc[0]),
                                fmaf(u4.y, Dd, yacc[1]),
                                fmaf(u4.z, Dd, yacc[2]),
                                fmaf(u4.w, Dd, yacc[3]));
        *(float4*)&y_out[((size_t)blk << 10) + p0] = yo;
    }
}

// ---------------------------------------------------------------------------
// Launch
// ---------------------------------------------------------------------------
extern "C" void kernel_launch(void* const* d_in, const int* in_sizes, int n_in,
                              void* d_out, int out_size) {
    const float* u_t      = (const float*)d_in[0];
    const float* s_prev   = (const float*)d_in[1];
    const float* gn_w     = (const float*)d_in[2];
    const float* gn_b     = (const float*)d_in[3];
    const float* cdw      = (const float*)d_in[4];
    const float* cdb      = (const float*)d_in[5];
    const float* cBw      = (const float*)d_in[6];
    const float* cCw      = (const float*)d_in[7];
    const float* logA     = (const float*)d_in[8];
    const float* D_param  = (const float*)d_in[9];
    const float* dt_bias  = (const float*)d_in[10];

    float* y_out = (float*)d_out;                              // (B,V,D,H,W)
    float* s_out = (float*)d_out + (size_t)B_ * V_ * D_ * HW;  // (B,V,D,N,H,W)

    k_stats_init<<<24, 1024>>>(u_t, logA);

    cudaLaunchAttribute attrs[1];
    attrs[0].id = cudaLaunchAttributeProgrammaticStreamSerialization;
    attrs[0].val.programmaticStreamSerializationAllowed = 1;

    {
        cudaLaunchConfig_t cfg = {};
        cfg.gridDim  = dim3(B_ * 24 * 4, 1, 1);
        cfg.blockDim = dim3(256, 1, 1);
        cfg.dynamicSmemBytes = 0;
        cfg.stream = 0;
        cfg.attrs = attrs;
        cfg.numAttrs = 1;
        cudaLaunchKernelEx(&cfg, k_conv, cdw, cdb, cBw, cCw, u_t, gn_w, gn_b, dt_bias);
    }
    {
        cudaLaunchConfig_t cfg = {};
        cfg.gridDim  = dim3(B_ * V_ * D_, 1, 1);
        cfg.blockDim = dim3(256, 1, 1);
        cfg.dynamicSmemBytes = 0;
        cfg.stream = 0;
        cfg.attrs = attrs;
        cfg.numAttrs = 1;
        cudaLaunchKernelEx(&cfg, k_main, s_prev, u_t, D_param, y_out, s_out);
    }
}